// round 1
// baseline (speedup 1.0000x reference)
#include <cuda_runtime.h>
#include <math.h>

#define NROWS 2048
#define HDIM  4096
#define VDIM  32000
#define BETA  0.5f

// ---------------- scratch (device globals; no allocations allowed) ----------
__device__ float g_logits[2][(size_t)NROWS * VDIM];   // 2 x 262 MB
__device__ float g_logZ[2][NROWS];
__device__ float g_rowjsd[NROWS];

// ---------------- GEMM: out[n][v] = sum_h X[n][h]*W[v][h] + b[v] ------------
// Block tile 128x128, K-tile 8, 256 threads, 8x8 micro-tile per thread.
#define BM 128
#define BN 128
#define BK 8
#define SPAD 136   // 136*4 = 544 bytes/row, multiple of 16 -> float4-aligned rows

__global__ __launch_bounds__(256) void gemm_bias_kernel(
    const float* __restrict__ X, const float* __restrict__ W,
    const float* __restrict__ bias, int which)
{
    __shared__ float As[BK][SPAD];
    __shared__ float Bs[BK][SPAD];

    float* out = g_logits[which];

    const int bm = blockIdx.y * BM;      // row block (N dim)
    const int bn = blockIdx.x * BN;      // col block (V dim)
    const int tid = threadIdx.x;
    const int ty = tid / 16;             // 0..15
    const int tx = tid % 16;             // 0..15

    // load mapping: each thread loads one float4; 256 threads cover 128 rows x 8 cols
    const int lrow = tid >> 1;           // 0..127
    const int lcol = (tid & 1) * 4;      // 0 or 4

    const float* aptr = X + (size_t)(bm + lrow) * HDIM + lcol;
    const float* bptr = W + (size_t)(bn + lrow) * HDIM + lcol;

    float acc[8][8];
    #pragma unroll
    for (int i = 0; i < 8; i++)
        #pragma unroll
        for (int j = 0; j < 8; j++) acc[i][j] = 0.f;

    for (int k0 = 0; k0 < HDIM; k0 += BK) {
        float4 a4 = *(const float4*)(aptr + k0);
        float4 b4 = *(const float4*)(bptr + k0);
        As[lcol + 0][lrow] = a4.x; As[lcol + 1][lrow] = a4.y;
        As[lcol + 2][lrow] = a4.z; As[lcol + 3][lrow] = a4.w;
        Bs[lcol + 0][lrow] = b4.x; Bs[lcol + 1][lrow] = b4.y;
        Bs[lcol + 2][lrow] = b4.z; Bs[lcol + 3][lrow] = b4.w;
        __syncthreads();

        #pragma unroll
        for (int k = 0; k < BK; k++) {
            float4 a0 = *(const float4*)&As[k][ty * 8];
            float4 a1 = *(const float4*)&As[k][ty * 8 + 4];
            float4 b0 = *(const float4*)&Bs[k][tx * 8];
            float4 b1 = *(const float4*)&Bs[k][tx * 8 + 4];
            float a[8] = {a0.x, a0.y, a0.z, a0.w, a1.x, a1.y, a1.z, a1.w};
            float b[8] = {b0.x, b0.y, b0.z, b0.w, b1.x, b1.y, b1.z, b1.w};
            #pragma unroll
            for (int i = 0; i < 8; i++)
                #pragma unroll
                for (int j = 0; j < 8; j++)
                    acc[i][j] = fmaf(a[i], b[j], acc[i][j]);
        }
        __syncthreads();
    }

    // epilogue: add bias, store
    float bv[8];
    #pragma unroll
    for (int j = 0; j < 8; j++) bv[j] = bias[bn + tx * 8 + j];

    #pragma unroll
    for (int i = 0; i < 8; i++) {
        const size_t row = (size_t)(bm + ty * 8 + i);
        float4 o0, o1;
        o0.x = acc[i][0] + bv[0]; o0.y = acc[i][1] + bv[1];
        o0.z = acc[i][2] + bv[2]; o0.w = acc[i][3] + bv[3];
        o1.x = acc[i][4] + bv[4]; o1.y = acc[i][5] + bv[5];
        o1.z = acc[i][6] + bv[6]; o1.w = acc[i][7] + bv[7];
        *(float4*)(out + row * VDIM + bn + tx * 8)     = o0;
        *(float4*)(out + row * VDIM + bn + tx * 8 + 4) = o1;
    }
}

// ---------------- per-row log-sum-exp (online, single pass) -----------------
__global__ __launch_bounds__(256) void rowstats_kernel()
{
    const int row   = blockIdx.x;
    const int which = blockIdx.y;
    const float* src = g_logits[which] + (size_t)row * VDIM;

    float m = -INFINITY, s = 0.f;
    for (int v = threadIdx.x; v < VDIM; v += 256) {
        float x = src[v];
        float M = fmaxf(m, x);
        s = s * expf(m - M) + expf(x - M);
        m = M;
    }

    // warp combine (m, s)
    #pragma unroll
    for (int o = 16; o > 0; o >>= 1) {
        float m2 = __shfl_down_sync(0xFFFFFFFFu, m, o);
        float s2 = __shfl_down_sync(0xFFFFFFFFu, s, o);
        float M = fmaxf(m, m2);
        s = s * expf(m - M) + s2 * expf(m2 - M);
        m = M;
    }
    __shared__ float sm[8], ss[8];
    const int lane = threadIdx.x & 31, warp = threadIdx.x >> 5;
    if (lane == 0) { sm[warp] = m; ss[warp] = s; }
    __syncthreads();
    if (warp == 0) {
        m = (lane < 8) ? sm[lane] : -INFINITY;
        s = (lane < 8) ? ss[lane] : 0.f;
        #pragma unroll
        for (int o = 4; o > 0; o >>= 1) {
            float m2 = __shfl_down_sync(0xFFFFFFFFu, m, o);
            float s2 = __shfl_down_sync(0xFFFFFFFFu, s, o);
            float M = fmaxf(m, m2);
            s = s * expf(m - M) + s2 * expf(m2 - M);
            m = M;
        }
        if (lane == 0) g_logZ[which][row] = m + logf(s);
    }
}

// ---------------- per-row generalized JSD -----------------------------------
__global__ __launch_bounds__(256) void jsd_row_kernel()
{
    const int row = blockIdx.x;
    const float zs = g_logZ[0][row];
    const float zt = g_logZ[1][row];
    const float* srow = g_logits[0] + (size_t)row * VDIM;
    const float* trow = g_logits[1] + (size_t)row * VDIM;

    float acc = 0.f;
    for (int v = threadIdx.x; v < VDIM; v += 256) {
        float lq = srow[v] - zs;          // student log-prob
        float lp = trow[v] - zt;          // teacher log-prob
        float q = expf(lq);
        float p = expf(lp);
        float lm = logf(BETA * p + (1.f - BETA) * q);
        acc += BETA * p * (lp - lm) + (1.f - BETA) * q * (lq - lm);
    }

    #pragma unroll
    for (int o = 16; o > 0; o >>= 1)
        acc += __shfl_down_sync(0xFFFFFFFFu, acc, o);
    __shared__ float sbuf[8];
    const int lane = threadIdx.x & 31, warp = threadIdx.x >> 5;
    if (lane == 0) sbuf[warp] = acc;
    __syncthreads();
    if (warp == 0) {
        acc = (lane < 8) ? sbuf[lane] : 0.f;
        #pragma unroll
        for (int o = 4; o > 0; o >>= 1)
            acc += __shfl_down_sync(0xFFFFFFFFu, acc, o);
        if (lane == 0) g_rowjsd[row] = acc;
    }
}

// ---------------- deterministic final mean ----------------------------------
__global__ __launch_bounds__(256) void finalize_kernel(float* out)
{
    float acc = 0.f;
    for (int r = threadIdx.x; r < NROWS; r += 256) acc += g_rowjsd[r];
    #pragma unroll
    for (int o = 16; o > 0; o >>= 1)
        acc += __shfl_down_sync(0xFFFFFFFFu, acc, o);
    __shared__ float sbuf[8];
    const int lane = threadIdx.x & 31, warp = threadIdx.x >> 5;
    if (lane == 0) sbuf[warp] = acc;
    __syncthreads();
    if (warp == 0) {
        acc = (lane < 8) ? sbuf[lane] : 0.f;
        #pragma unroll
        for (int o = 4; o > 0; o >>= 1)
            acc += __shfl_down_sync(0xFFFFFFFFu, acc, o);
        if (lane == 0) out[0] = acc / (float)NROWS;
    }
}

// ---------------- launch ----------------------------------------------------
extern "C" void kernel_launch(void* const* d_in, const int* in_sizes, int n_in,
                              void* d_out, int out_size)
{
    const float* Xs = (const float*)d_in[0];   // student_input [2048,4096]
    const float* Xt = (const float*)d_in[1];   // teacher_input [2048,4096]
    const float* Ws = (const float*)d_in[2];   // W_student [32000,4096]
    const float* bs = (const float*)d_in[3];   // b_student [32000]
    const float* Wt = (const float*)d_in[4];   // W_teacher [32000,4096]
    const float* bt = (const float*)d_in[5];   // b_teacher [32000]
    float* out = (float*)d_out;

    dim3 ggrid(VDIM / BN, NROWS / BM);         // (250, 16)
    gemm_bias_kernel<<<ggrid, 256>>>(Xs, Ws, bs, 0);
    gemm_bias_kernel<<<ggrid, 256>>>(Xt, Wt, bt, 1);
    rowstats_kernel<<<dim3(NROWS, 2), 256>>>();
    jsd_row_kernel<<<NROWS, 256>>>();
    finalize_kernel<<<1, 256>>>(out);
}

// round 6
// speedup vs baseline: 3.2991x; 3.2991x over previous
#include <cuda_runtime.h>
#include <cstdint>
#include <math.h>

#define NROWS 2048
#define HDIM  4096
#define VDIM  32000
#define BETA  0.5f

// ---- GEMM tiling (Ampere-style mma.sync tf32) ----
#define BM 128
#define BN 128
#define BK 32
#define NITER (HDIM / BK)            // 128
#define STAGES 3
#define KPITCH 36                     // floats per row in smem (36*4=144B, 16B-aligned)
#define STAGE_FLOATS (256 * KPITCH)   // A(128 rows) + B(128 rows)
#define STAGE_BYTES (STAGE_FLOATS * 4)        // 36864
#define SMEM_DYN (STAGES * STAGE_BYTES)       // 110592

// ---------------- scratch (device globals; no allocations allowed) ----------
__device__ float g_Xr[2][(size_t)NROWS * HDIM];     // tf32-rounded inputs
__device__ float g_Wr[2][(size_t)VDIM * HDIM];      // tf32-rounded weights
__device__ float g_logits[2][(size_t)NROWS * VDIM];
__device__ float g_logZ[2][NROWS];
__device__ float g_rowjsd[NROWS];

// ---------------- PTX helpers ----------------------------------------------
__device__ __forceinline__ uint32_t smem_u32(const void* p) {
    uint32_t r;
    asm("{ .reg .u64 t; cvta.to.shared.u64 t, %1; cvt.u32.u64 %0, t; }"
        : "=r"(r) : "l"(p));
    return r;
}

#define CP_ASYNC16(dst, src) \
    asm volatile("cp.async.cg.shared.global [%0], [%1], 16;" \
                 :: "r"(dst), "l"(src) : "memory")
#define CP_COMMIT() asm volatile("cp.async.commit_group;" ::: "memory")
#define CP_WAIT(n)  asm volatile("cp.async.wait_group %0;" :: "n"(n) : "memory")

// D = A(16x8,row) * B(8x8,col) + D, tf32 in, f32 out
#define MMA_TF32(c, a, b)                                                     \
    asm volatile("mma.sync.aligned.m16n8k8.row.col.f32.tf32.tf32.f32 "        \
        "{%0,%1,%2,%3}, {%4,%5,%6,%7}, {%8,%9}, {%0,%1,%2,%3};"               \
        : "+f"((c)[0]), "+f"((c)[1]), "+f"((c)[2]), "+f"((c)[3])              \
        : "r"((a)[0]), "r"((a)[1]), "r"((a)[2]), "r"((a)[3]),                 \
          "r"((b)[0]), "r"((b)[1]))

// ---------------- tf32 round-to-nearest pre-pass ----------------------------
__device__ __forceinline__ float rna_tf32(float x) {
    uint32_t o;
    asm("cvt.rna.tf32.f32 %0, %1;" : "=r"(o) : "f"(x));
    return __uint_as_float(o);
}
__global__ __launch_bounds__(256) void rnd_w_kernel(const float4* __restrict__ in, int which) {
    float4* out = (float4*)g_Wr[which];
    const int n4 = (int)((size_t)VDIM * HDIM / 4);
    const int stride = gridDim.x * blockDim.x;
    for (int i = blockIdx.x * blockDim.x + threadIdx.x; i < n4; i += stride) {
        float4 v = in[i];
        out[i] = make_float4(rna_tf32(v.x), rna_tf32(v.y), rna_tf32(v.z), rna_tf32(v.w));
    }
}
__global__ __launch_bounds__(256) void rnd_x_kernel(const float4* __restrict__ in, int which) {
    float4* out = (float4*)g_Xr[which];
    const int n4 = (int)((size_t)NROWS * HDIM / 4);
    const int stride = gridDim.x * blockDim.x;
    for (int i = blockIdx.x * blockDim.x + threadIdx.x; i < n4; i += stride) {
        float4 v = in[i];
        out[i] = make_float4(rna_tf32(v.x), rna_tf32(v.y), rna_tf32(v.z), rna_tf32(v.w));
    }
}

// ---------------- mma.sync tf32 GEMM: logits = Xr @ Wr^T + b -----------------
// 256 threads, 8 warps in 2x4 (warp tile 64x32), cp.async 3-stage pipeline.
__device__ __forceinline__ void load_stage(uint32_t sbase, const float* __restrict__ ga,
                                           const float* __restrict__ gb, int tid)
{
    #pragma unroll
    for (int i = 0; i < 4; i++) {            // A: 128 rows x 8 x 16B chunks
        int idx = tid + i * 256;
        int row = idx >> 3, ch = idx & 7;
        CP_ASYNC16(sbase + row * 144 + ch * 16, ga + (size_t)row * HDIM + ch * 4);
    }
    #pragma unroll
    for (int i = 0; i < 4; i++) {            // B: 128 rows x 8 x 16B chunks
        int idx = tid + i * 256;
        int row = idx >> 3, ch = idx & 7;
        CP_ASYNC16(sbase + 128 * 144 + row * 144 + ch * 16, gb + (size_t)row * HDIM + ch * 4);
    }
}

__global__ __launch_bounds__(256, 1) void gemm_mma(int which, const float* __restrict__ bias)
{
    extern __shared__ __align__(16) float smem[];
    const uint32_t sb = smem_u32(smem);

    const float* X = g_Xr[which];
    const float* W = g_Wr[which];
    float* out = g_logits[which];

    const int bm = blockIdx.x * BM;
    const int bn = blockIdx.y * BN;
    const int tid = threadIdx.x;
    const int wid = tid >> 5;
    const int lane = tid & 31;
    const int wm = (wid >> 2) * 64;          // warp row offset in tile
    const int wn = (wid & 3) * 32;           // warp col offset in tile
    const int lr = lane >> 2;                // 0..7
    const int lc = lane & 3;                 // 0..3

    const float* ga = X + (size_t)bm * HDIM;
    const float* gb = W + (size_t)bn * HDIM;

    float acc[4][4][4];
    #pragma unroll
    for (int mt = 0; mt < 4; mt++)
        #pragma unroll
        for (int nt = 0; nt < 4; nt++)
            #pragma unroll
            for (int j = 0; j < 4; j++) acc[mt][nt][j] = 0.f;

    // prologue: preload STAGES-1 stages
    #pragma unroll
    for (int c = 0; c < STAGES - 1; c++) {
        load_stage(sb + c * STAGE_BYTES, ga + c * BK, gb + c * BK, tid);
        CP_COMMIT();
    }

    int sc = 0;  // stage of current compute
    for (int c = 0; c < NITER; c++) {
        CP_WAIT(STAGES - 2);
        __syncthreads();

        // issue loads for stage c+STAGES-1 (buffer freed at end of prev iter)
        int cn = c + STAGES - 1;
        if (cn < NITER) {
            int sl = cn % STAGES;
            load_stage(sb + sl * STAGE_BYTES, ga + cn * BK, gb + cn * BK, tid);
        }
        CP_COMMIT();

        // compute on stage sc
        const float* As = smem + sc * STAGE_FLOATS;
        const float* Bs = As + 128 * KPITCH;
        #pragma unroll
        for (int ks = 0; ks < 4; ks++) {
            const int k0 = ks * 8 + lc;
            uint32_t a[4][4], b[4][2];
            #pragma unroll
            for (int mt = 0; mt < 4; mt++) {
                const float* ap = As + (wm + mt * 16 + lr) * KPITCH + k0;
                a[mt][0] = __float_as_uint(ap[0]);
                a[mt][1] = __float_as_uint(ap[8 * KPITCH]);
                a[mt][2] = __float_as_uint(ap[4]);
                a[mt][3] = __float_as_uint(ap[8 * KPITCH + 4]);
            }
            #pragma unroll
            for (int nt = 0; nt < 4; nt++) {
                const float* bp = Bs + (wn + nt * 8 + lr) * KPITCH + k0;
                b[nt][0] = __float_as_uint(bp[0]);
                b[nt][1] = __float_as_uint(bp[4]);
            }
            #pragma unroll
            for (int mt = 0; mt < 4; mt++)
                #pragma unroll
                for (int nt = 0; nt < 4; nt++)
                    MMA_TF32(acc[mt][nt], a[mt], b[nt]);
        }
        __syncthreads();   // all warps done with stage sc before it's refilled
        if (++sc == STAGES) sc = 0;
    }
    CP_WAIT(0);

    // epilogue: add bias, store
    #pragma unroll
    for (int mt = 0; mt < 4; mt++) {
        const int r0 = bm + wm + mt * 16 + lr;
        #pragma unroll
        for (int nt = 0; nt < 4; nt++) {
            const int col = bn + wn + nt * 8 + (lc << 1);
            float2 bv = *(const float2*)(bias + col);
            float2 v0, v1;
            v0.x = acc[mt][nt][0] + bv.x; v0.y = acc[mt][nt][1] + bv.y;
            v1.x = acc[mt][nt][2] + bv.x; v1.y = acc[mt][nt][3] + bv.y;
            *(float2*)(out + (size_t)r0 * VDIM + col) = v0;
            *(float2*)(out + (size_t)(r0 + 8) * VDIM + col) = v1;
        }
    }
}

// ---------------- per-row log-sum-exp (online, single pass) -----------------
__global__ __launch_bounds__(256) void rowstats_kernel()
{
    const int row   = blockIdx.x;
    const int which = blockIdx.y;
    const float* src = g_logits[which] + (size_t)row * VDIM;

    float m = -INFINITY, s = 0.f;
    for (int v = threadIdx.x; v < VDIM; v += 256) {
        float x = src[v];
        float M = fmaxf(m, x);
        s = s * expf(m - M) + expf(x - M);
        m = M;
    }
    #pragma unroll
    for (int o = 16; o > 0; o >>= 1) {
        float m2 = __shfl_down_sync(0xFFFFFFFFu, m, o);
        float s2 = __shfl_down_sync(0xFFFFFFFFu, s, o);
        float M = fmaxf(m, m2);
        s = s * expf(m - M) + s2 * expf(m2 - M);
        m = M;
    }
    __shared__ float sm[8], ss[8];
    const int lane = threadIdx.x & 31, warp = threadIdx.x >> 5;
    if (lane == 0) { sm[warp] = m; ss[warp] = s; }
    __syncthreads();
    if (warp == 0) {
        m = (lane < 8) ? sm[lane] : -INFINITY;
        s = (lane < 8) ? ss[lane] : 0.f;
        #pragma unroll
        for (int o = 4; o > 0; o >>= 1) {
            float m2 = __shfl_down_sync(0xFFFFFFFFu, m, o);
            float s2 = __shfl_down_sync(0xFFFFFFFFu, s, o);
            float M = fmaxf(m, m2);
            s = s * expf(m - M) + s2 * expf(m2 - M);
            m = M;
        }
        if (lane == 0) g_logZ[which][row] = m + logf(s);
    }
}

// ---------------- per-row generalized JSD -----------------------------------
__global__ __launch_bounds__(256) void jsd_row_kernel()
{
    const int row = blockIdx.x;
    const float zs = g_logZ[0][row];
    const float zt = g_logZ[1][row];
    const float* srow = g_logits[0] + (size_t)row * VDIM;
    const float* trow = g_logits[1] + (size_t)row * VDIM;

    float acc = 0.f;
    for (int v = threadIdx.x; v < VDIM; v += 256) {
        float lq = srow[v] - zs;
        float lp = trow[v] - zt;
        float q = expf(lq);
        float p = expf(lp);
        float lm = logf(BETA * p + (1.f - BETA) * q);
        acc += BETA * p * (lp - lm) + (1.f - BETA) * q * (lq - lm);
    }
    #pragma unroll
    for (int o = 16; o > 0; o >>= 1)
        acc += __shfl_down_sync(0xFFFFFFFFu, acc, o);
    __shared__ float sbuf[8];
    const int lane = threadIdx.x & 31, warp = threadIdx.x >> 5;
    if (lane == 0) sbuf[warp] = acc;
    __syncthreads();
    if (warp == 0) {
        acc = (lane < 8) ? sbuf[lane] : 0.f;
        #pragma unroll
        for (int o = 4; o > 0; o >>= 1)
            acc += __shfl_down_sync(0xFFFFFFFFu, acc, o);
        if (lane == 0) g_rowjsd[row] = acc;
    }
}

// ---------------- deterministic final mean ----------------------------------
__global__ __launch_bounds__(256) void finalize_kernel(float* out)
{
    float acc = 0.f;
    for (int r = threadIdx.x; r < NROWS; r += 256) acc += g_rowjsd[r];
    #pragma unroll
    for (int o = 16; o > 0; o >>= 1)
        acc += __shfl_down_sync(0xFFFFFFFFu, acc, o);
    __shared__ float sbuf[8];
    const int lane = threadIdx.x & 31, warp = threadIdx.x >> 5;
    if (lane == 0) sbuf[warp] = acc;
    __syncthreads();
    if (warp == 0) {
        acc = (lane < 8) ? sbuf[lane] : 0.f;
        #pragma unroll
        for (int o = 4; o > 0; o >>= 1)
            acc += __shfl_down_sync(0xFFFFFFFFu, acc, o);
        if (lane == 0) out[0] = acc / (float)NROWS;
    }
}

// ---------------- launch ----------------------------------------------------
extern "C" void kernel_launch(void* const* d_in, const int* in_sizes, int n_in,
                              void* d_out, int out_size)
{
    const float* Xs = (const float*)d_in[0];
    const float* Xt = (const float*)d_in[1];
    const float* Ws = (const float*)d_in[2];
    const float* bs = (const float*)d_in[3];
    const float* Wt = (const float*)d_in[4];
    const float* bt = (const float*)d_in[5];
    float* out = (float*)d_out;

    cudaFuncSetAttribute(gemm_mma, cudaFuncAttributeMaxDynamicSharedMemorySize, SMEM_DYN);

    rnd_x_kernel<<<1024, 256>>>((const float4*)Xs, 0);
    rnd_x_kernel<<<1024, 256>>>((const float4*)Xt, 1);
    rnd_w_kernel<<<8192, 256>>>((const float4*)Ws, 0);
    rnd_w_kernel<<<8192, 256>>>((const float4*)Wt, 1);

    dim3 ggrid(NROWS / BM, VDIM / BN);   // (16, 250): x-adjacent CTAs share W panel in L2
    gemm_mma<<<ggrid, 256, SMEM_DYN>>>(0, bs);
    gemm_mma<<<ggrid, 256, SMEM_DYN>>>(1, bt);

    rowstats_kernel<<<dim3(NROWS, 2), 256>>>();
    jsd_row_kernel<<<NROWS, 256>>>();
    finalize_kernel<<<1, 256>>>(out);
}